// round 2
// baseline (speedup 1.0000x reference)
#include <cuda_runtime.h>

// ---------------------------------------------------------------------------
// LearnableWaveletTransform: 3-level channel-wise db4 DWT (zero-padding mode)
// x: [B=8, S=4096, F=128] f32  ->  out: [6, B, 4096, F] f32
// slots: [approx(lo3), d1(hi1), d2(hi2), d3(hi3), d1+d2+d3, lo3]
//
// Per level (correlation with reversed dec filter, stride 2, left pad 6):
//   out[n] = sum_{t=0..7} Krev[t] * x[2n - 6 + t],  x==0 outside [0, S_in)
// Coefficient lengths: 4096 -> 2051 -> 1029 -> 518
// ---------------------------------------------------------------------------

#define NB   8
#define S_0  4096
#define S_1  2051
#define S_2  1029
#define S_3  518
#define F4   32          // 128 floats = 32 float4

// Scratch (device globals: allowed; cudaMalloc is not)
__device__ float4 g_lo1[NB * S_1 * F4];
__device__ float4 g_hi1[NB * S_1 * F4];
__device__ float4 g_lo2[NB * S_2 * F4];
__device__ float4 g_hi2[NB * S_2 * F4];
__device__ float4 g_lo3[NB * S_3 * F4];
__device__ float4 g_hi3[NB * S_3 * F4];

// Reversed db4 decomposition filters (the correlation kernels)
__constant__ float c_lo[8] = {
     0.23037781330885523f,  0.7148465705525415f,   0.6308807679295904f,
    -0.02798376941698385f, -0.18703481171888114f,  0.030841381835986965f,
     0.032883011666982945f, -0.010597401784997278f };
__constant__ float c_hi[8] = {
    -0.010597401784997278f, 0.032883011666982945f, 0.030841381835986965f,
     0.18703481171888114f, -0.02798376941698385f, -0.6308807679295904f,
     0.7148465705525415f,  -0.23037781330885523f };

__device__ __forceinline__ void fma4(float4& a, float c, const float4& v) {
    a.x = fmaf(c, v.x, a.x);
    a.y = fmaf(c, v.y, a.y);
    a.z = fmaf(c, v.z, a.z);
    a.w = fmaf(c, v.w, a.w);
}

template <int LEVEL>
__global__ void dwt_level_k(const float4* __restrict__ x_ext) {
    constexpr int S_in  = (LEVEL == 1) ? S_0 : (LEVEL == 2) ? S_1 : S_2;
    constexpr int S_out = (LEVEL == 1) ? S_1 : (LEVEL == 2) ? S_2 : S_3;

    const float4* __restrict__ in =
        (LEVEL == 1) ? x_ext : (LEVEL == 2) ? (const float4*)g_lo1 : (const float4*)g_lo2;
    float4* __restrict__ lo = (LEVEL == 1) ? g_lo1 : (LEVEL == 2) ? g_lo2 : g_lo3;
    float4* __restrict__ hi = (LEVEL == 1) ? g_hi1 : (LEVEL == 2) ? g_hi2 : g_hi3;

    const int f4 = threadIdx.x;                              // 0..31
    const int n  = blockIdx.x * blockDim.y + threadIdx.y;    // output position
    const int b  = blockIdx.y;
    if (n >= S_out) return;

    const float4* __restrict__ inb = in + (size_t)b * S_in * F4;

    float4 alo = make_float4(0.f, 0.f, 0.f, 0.f);
    float4 ahi = make_float4(0.f, 0.f, 0.f, 0.f);

    const int s0 = 2 * n - 6;
#pragma unroll
    for (int t = 0; t < 8; ++t) {
        const int s = s0 + t;
        if (s >= 0 && s < S_in) {
            const float4 v = __ldg(&inb[s * F4 + f4]);
            fma4(alo, c_lo[t], v);
            fma4(ahi, c_hi[t], v);
        }
    }

    const int o = (b * S_out + n) * F4 + f4;
    lo[o] = alo;
    hi[o] = ahi;
}

// One thread per output float4; total = 6*8*4096*32 = 6,291,456 = 24576 * 256
__global__ void assemble_k(float4* __restrict__ out) {
    const int idx  = blockIdx.x * 256 + threadIdx.x;
    const int f4   = idx & 31;
    const int s    = (idx >> 5) & 4095;
    const int b    = (idx >> 17) & 7;
    const int slot = idx >> 20;

    float4 v = make_float4(0.f, 0.f, 0.f, 0.f);

    if (slot == 0 || slot == 5) {
        if (s < S_3) v = g_lo3[(b * S_3 + s) * F4 + f4];
    } else if (slot == 1) {
        if (s < S_1) v = g_hi1[(b * S_1 + s) * F4 + f4];
    } else if (slot == 2) {
        if (s < S_2) v = g_hi2[(b * S_2 + s) * F4 + f4];
    } else if (slot == 3) {
        if (s < S_3) v = g_hi3[(b * S_3 + s) * F4 + f4];
    } else {  // slot == 4 : d1 + d2 + d3 (each zero-extended)
        if (s < S_1) {
            v = g_hi1[(b * S_1 + s) * F4 + f4];
            if (s < S_2) {
                const float4 w = g_hi2[(b * S_2 + s) * F4 + f4];
                v.x += w.x; v.y += w.y; v.z += w.z; v.w += w.w;
            }
            if (s < S_3) {
                const float4 w = g_hi3[(b * S_3 + s) * F4 + f4];
                v.x += w.x; v.y += w.y; v.z += w.z; v.w += w.w;
            }
        }
    }
    out[idx] = v;
}

extern "C" void kernel_launch(void* const* d_in, const int* in_sizes, int n_in,
                              void* d_out, int out_size) {
    const float4* x = (const float4*)d_in[0];
    float4* out     = (float4*)d_out;

    const dim3 blk(32, 8);  // 32 f4-lanes x 8 output positions = 256 threads
    dwt_level_k<1><<<dim3((S_1 + 7) / 8, NB), blk>>>(x);
    dwt_level_k<2><<<dim3((S_2 + 7) / 8, NB), blk>>>(nullptr);
    dwt_level_k<3><<<dim3((S_3 + 7) / 8, NB), blk>>>(nullptr);

    assemble_k<<<24576, 256>>>(out);
}

// round 3
// speedup vs baseline: 1.2307x; 1.2307x over previous
#include <cuda_runtime.h>

// ---------------------------------------------------------------------------
// LearnableWaveletTransform, fully fused: 3-level channel-wise db4 DWT
// (zero-padding mode) with the level-2/3 cascades collapsed into composed
// direct filters on x. One kernel, no scratch.
//
//   x: [B=8, S=4096, F=128] f32  ->  out: [6, B, 4096, F] f32
//   slots: [lo3, hi1, hi2, hi3, hi1+hi2+hi3, lo3]
//
//   hi1[s] = sum_{j=0..7}  Khi[j]       * x[2s-6  + j]
//   hi2[s] = sum_{j=0..21} C2hi[j]      * x[4s-18 + j]   (C2 = Khi o Klo)
//   lo3[s] = sum_{j=0..49} C3lo[j]      * x[8s-42 + j]   (C3 = K o Klo o Klo)
//   (x zero-extended; self-zeroing beyond coeff lengths 2051/1029/518)
// ---------------------------------------------------------------------------

#define NB   8
#define S0   4096
#define F4   32                       // 128 floats = 32 float4
#define SLOT ((size_t)NB * S0 * F4)   // float4 elements per output slot

// Reversed db4 decomposition filters (the correlation kernels)
__constant__ float c_lo[8] = {
     0.23037781330885523f,  0.7148465705525415f,   0.6308807679295904f,
    -0.02798376941698385f, -0.18703481171888114f,  0.030841381835986965f,
     0.032883011666982945f, -0.010597401784997278f };
__constant__ float c_hi[8] = {
    -0.010597401784997278f, 0.032883011666982945f, 0.030841381835986965f,
     0.18703481171888114f, -0.02798376941698385f, -0.6308807679295904f,
     0.7148465705525415f,  -0.23037781330885523f };

__device__ __forceinline__ void fma4(float4& a, float c, const float4& v) {
    a.x = fmaf(c, v.x, a.x);
    a.y = fmaf(c, v.y, a.y);
    a.z = fmaf(c, v.z, a.z);
    a.w = fmaf(c, v.w, a.w);
}

__global__ void wavelet_fused_k(const float4* __restrict__ x,
                                float4* __restrict__ out) {
    __shared__ float sC2lo[22], sC2hi[22], sC3lo[50], sC3hi[50];

    const int tid = threadIdx.y * 32 + threadIdx.x;

    // Build composed filters (cheap, per-block).
    if (tid < 22) {
        float alo = 0.f, ahi = 0.f;
#pragma unroll
        for (int u = 0; u < 8; ++u) {
            const int t = tid - 2 * u;
            if (t >= 0 && t < 8) {
                alo += c_lo[u] * c_lo[t];   // lo applied after lo
                ahi += c_hi[u] * c_lo[t];   // hi applied after lo
            }
        }
        sC2lo[tid] = alo;
        sC2hi[tid] = ahi;
    }
    __syncthreads();
    if (tid < 50) {
        float alo = 0.f, ahi = 0.f;
#pragma unroll
        for (int v = 0; v < 8; ++v) {
            const int j = tid - 4 * v;
            if (j >= 0 && j < 22) {
                alo += c_lo[v] * sC2lo[j];
                ahi += c_hi[v] * sC2lo[j];
            }
        }
        sC3lo[tid] = alo;
        sC3hi[tid] = ahi;
    }
    __syncthreads();

    const int f4 = threadIdx.x;                            // 0..31
    const int s  = blockIdx.x * blockDim.y + threadIdx.y;  // 0..4095
    const int b  = blockIdx.y;

    const float4* __restrict__ xb = x + (size_t)b * S0 * F4 + f4;

    float4 h1 = make_float4(0.f, 0.f, 0.f, 0.f);
    float4 h2 = make_float4(0.f, 0.f, 0.f, 0.f);
    float4 l3 = make_float4(0.f, 0.f, 0.f, 0.f);
    float4 h3 = make_float4(0.f, 0.f, 0.f, 0.f);

    // Level-1 hi (slot 1): 8 taps, stride 2
    if (s < 2051) {
        const int s0  = 2 * s - 6;
        const int jlo = max(0, -s0);
        const int jhi = min(8, S0 - s0);
#pragma unroll
        for (int j = 0; j < 8; ++j) {
            if (j >= jlo && j < jhi) {
                const float4 v = __ldg(xb + (size_t)(s0 + j) * F4);
                fma4(h1, c_hi[j], v);
            }
        }
    }

    // Level-2 hi (slot 2): 22 composed taps, stride 4
    if (s < 1029) {
        const int s0  = 4 * s - 18;
        const int jlo = max(0, -s0);
        const int jhi = min(22, S0 - s0);
        for (int j = jlo; j < jhi; ++j) {
            const float4 v = __ldg(xb + (size_t)(s0 + j) * F4);
            fma4(h2, sC2hi[j], v);
        }
    }

    // Level-3 lo & hi (slots 0/5 and 3): 50 composed taps, stride 8, shared loads
    if (s < 518) {
        const int s0  = 8 * s - 42;
        const int jlo = max(0, -s0);
        const int jhi = min(50, S0 - s0);
        for (int j = jlo; j < jhi; ++j) {
            const float4 v = __ldg(xb + (size_t)(s0 + j) * F4);
            fma4(l3, sC3lo[j], v);
            fma4(h3, sC3hi[j], v);
        }
    }

    float4 hf;
    hf.x = h1.x + h2.x + h3.x;
    hf.y = h1.y + h2.y + h3.y;
    hf.z = h1.z + h2.z + h3.z;
    hf.w = h1.w + h2.w + h3.w;

    const size_t o = ((size_t)(b * S0 + s)) * F4 + f4;
    __stcs(out + 0 * SLOT + o, l3);   // approx
    __stcs(out + 1 * SLOT + o, h1);   // d1
    __stcs(out + 2 * SLOT + o, h2);   // d2
    __stcs(out + 3 * SLOT + o, h3);   // d3
    __stcs(out + 4 * SLOT + o, hf);   // high_freq
    __stcs(out + 5 * SLOT + o, l3);   // low_freq
}

extern "C" void kernel_launch(void* const* d_in, const int* in_sizes, int n_in,
                              void* d_out, int out_size) {
    const float4* x = (const float4*)d_in[0];
    float4* out     = (float4*)d_out;

    const dim3 blk(32, 8);                 // 32 f4-lanes x 8 seq positions
    wavelet_fused_k<<<dim3(S0 / 8, NB), blk>>>(x, out);
}

// round 6
// speedup vs baseline: 1.3337x; 1.0837x over previous
#include <cuda_runtime.h>

// ---------------------------------------------------------------------------
// LearnableWaveletTransform, fused + s-register-tiled (R=4 outputs/thread).
// 3-level channel-wise db4 DWT (zero-padding mode), cascades collapsed into
// composed direct filters on x built at compile time.
//
//   x: [B=8, S=4096, F=128] f32  ->  out: [6, B, 4096, F] f32
//   slots: [lo3, hi1, hi2, hi3, hi1+hi2+hi3, lo3]
//
//   hi1[s] = sum_{j<8}  Khi[j]  * x[2s-6  + j]      (s < 2051)
//   hi2[s] = sum_{j<22} C2hi[j] * x[4s-18 + j]      (s < 1029)
//   lo3[s] = sum_{j<50} C3lo[j] * x[8s-42 + j]      (s < 518)   (hi3 same taps)
// ---------------------------------------------------------------------------

#define NB     8
#define S0     4096
#define F4     32                          // 128 floats = 32 float4
#define SLOTSZ ((size_t)NB * S0 * F4)      // float4 elems per output slot
#define RT     4                           // s positions per thread
#define TS     32                          // s positions per block (8 warps * RT)

struct Filt {
    float Klo[8], Khi[8], C2lo[22], C2hi[22], C3lo[50], C3hi[50];
    constexpr Filt()
        : Klo{ 0.23037781330885523f,  0.7148465705525415f,   0.6308807679295904f,
              -0.02798376941698385f, -0.18703481171888114f,  0.030841381835986965f,
               0.032883011666982945f, -0.010597401784997278f },
          Khi{ -0.010597401784997278f, 0.032883011666982945f, 0.030841381835986965f,
                0.18703481171888114f, -0.02798376941698385f, -0.6308807679295904f,
                0.7148465705525415f,  -0.23037781330885523f },
          C2lo{}, C2hi{}, C3lo{}, C3hi{} {
        for (int j = 0; j < 22; ++j) {
            float alo = 0.f, ahi = 0.f;
            for (int u = 0; u < 8; ++u) {
                const int t = j - 2 * u;
                if (t >= 0 && t < 8) { alo += Klo[u] * Klo[t]; ahi += Khi[u] * Klo[t]; }
            }
            C2lo[j] = alo; C2hi[j] = ahi;
        }
        for (int j = 0; j < 50; ++j) {
            float alo = 0.f, ahi = 0.f;
            for (int v = 0; v < 8; ++v) {
                const int t = j - 4 * v;
                if (t >= 0 && t < 22) { alo += Klo[v] * C2lo[t]; ahi += Khi[v] * C2lo[t]; }
            }
            C3lo[j] = alo; C3hi[j] = ahi;
        }
    }
};
__constant__ Filt FF = Filt();

__device__ __forceinline__ void fma4(float4& a, float c, const float4& v) {
    a.x = fmaf(c, v.x, a.x); a.y = fmaf(c, v.y, a.y);
    a.z = fmaf(c, v.z, a.z); a.w = fmaf(c, v.w, a.w);
}
__device__ __forceinline__ void add4(float4& a, const float4& v) {
    a.x += v.x; a.y += v.y; a.z += v.z; a.w += v.w;
}
__device__ __forceinline__ float4 zero4() { return make_float4(0.f, 0.f, 0.f, 0.f); }

__global__ __launch_bounds__(256)
void wavelet_rt_k(const float4* __restrict__ x, float4* __restrict__ out) {
    const int f4 = threadIdx.x;                           // 0..31 (feature/4)
    const int sb = blockIdx.x * TS + threadIdx.y * RT;    // first s of this thread
    const int b  = blockIdx.y;

    const float4* __restrict__ xb = x + (size_t)b * (S0 * F4) + f4;
    const size_t obase = ((size_t)(b * S0 + sb)) * F4 + f4;

    float4 hf[RT];
#pragma unroll
    for (int r = 0; r < RT; ++r) hf[r] = zero4();

    // ---------------- level 1: hi1 -> slot 1 (len 2051) ----------------
    {
        float4 acc[RT];
#pragma unroll
        for (int r = 0; r < RT; ++r) acc[r] = zero4();
        const int base = 2 * sb - 6;                      // span 14
        if (base >= 0 && base + 14 <= S0) {               // interior (s<=2047)
#pragma unroll
            for (int k = 0; k < 14; ++k) {
                const float4 v = __ldg(xb + (size_t)(base + k) * F4);
#pragma unroll
                for (int r = 0; r < RT; ++r) {
                    const int j = k - 2 * r;
                    if (j >= 0 && j < 8) fma4(acc[r], FF.Khi[j], v);
                }
            }
        } else if (sb < 2051) {                           // boundary
#pragma unroll
            for (int k = 0; k < 14; ++k) {
                const int xs = base + k;
                if (xs >= 0 && xs < S0) {
                    const float4 v = __ldg(xb + (size_t)xs * F4);
#pragma unroll
                    for (int r = 0; r < RT; ++r) {
                        const int j = k - 2 * r;
                        if (j >= 0 && j < 8 && (sb + r) < 2051)
                            fma4(acc[r], FF.Khi[j], v);
                    }
                }
            }
        }
#pragma unroll
        for (int r = 0; r < RT; ++r) {
            __stcs(out + 1 * SLOTSZ + obase + (size_t)r * F4, acc[r]);
            add4(hf[r], acc[r]);
        }
    }

    // ---------------- level 2: hi2 -> slot 2 (len 1029) ----------------
    {
        float4 acc[RT];
#pragma unroll
        for (int r = 0; r < RT; ++r) acc[r] = zero4();
        const int base = 4 * sb - 18;                     // span 34
        if (base >= 0 && base + 34 <= S0) {               // interior (8<=sb<=1020)
#pragma unroll
            for (int k = 0; k < 34; ++k) {
                const float4 v = __ldg(xb + (size_t)(base + k) * F4);
#pragma unroll
                for (int r = 0; r < RT; ++r) {
                    const int j = k - 4 * r;
                    if (j >= 0 && j < 22) fma4(acc[r], FF.C2hi[j], v);
                }
            }
        } else if (sb < 1029) {                           // boundary
#pragma unroll
            for (int k = 0; k < 34; ++k) {
                const int xs = base + k;
                if (xs >= 0 && xs < S0) {
                    const float4 v = __ldg(xb + (size_t)xs * F4);
#pragma unroll
                    for (int r = 0; r < RT; ++r) {
                        const int j = k - 4 * r;
                        if (j >= 0 && j < 22 && (sb + r) < 1029)
                            fma4(acc[r], FF.C2hi[j], v);
                    }
                }
            }
        }
#pragma unroll
        for (int r = 0; r < RT; ++r) {
            __stcs(out + 2 * SLOTSZ + obase + (size_t)r * F4, acc[r]);
            add4(hf[r], acc[r]);
        }
    }

    // -------- level 3: lo3 -> slots 0,5 ; hi3 -> slot 3 (len 518) --------
    {
        float4 al[RT], ah[RT];
#pragma unroll
        for (int r = 0; r < RT; ++r) { al[r] = zero4(); ah[r] = zero4(); }
        const int base = 8 * sb - 42;                     // span 74
        if (base >= 0 && base + 74 <= S0) {               // interior (8<=sb<=508)
#pragma unroll
            for (int k = 0; k < 74; ++k) {
                const float4 v = __ldg(xb + (size_t)(base + k) * F4);
#pragma unroll
                for (int r = 0; r < RT; ++r) {
                    const int j = k - 8 * r;
                    if (j >= 0 && j < 50) {
                        fma4(al[r], FF.C3lo[j], v);
                        fma4(ah[r], FF.C3hi[j], v);
                    }
                }
            }
        } else if (sb < 518) {                            // boundary
#pragma unroll
            for (int k = 0; k < 74; ++k) {
                const int xs = base + k;
                if (xs >= 0 && xs < S0) {
                    const float4 v = __ldg(xb + (size_t)xs * F4);
#pragma unroll
                    for (int r = 0; r < RT; ++r) {
                        const int j = k - 8 * r;
                        if (j >= 0 && j < 50 && (sb + r) < 518) {
                            fma4(al[r], FF.C3lo[j], v);
                            fma4(ah[r], FF.C3hi[j], v);
                        }
                    }
                }
            }
        }
#pragma unroll
        for (int r = 0; r < RT; ++r) {
            const size_t o = obase + (size_t)r * F4;
            __stcs(out + 0 * SLOTSZ + o, al[r]);
            __stcs(out + 3 * SLOTSZ + o, ah[r]);
            __stcs(out + 5 * SLOTSZ + o, al[r]);
            add4(hf[r], ah[r]);
        }
    }

    // ---------------- slot 4: hi1 + hi2 + hi3 ----------------
#pragma unroll
    for (int r = 0; r < RT; ++r)
        __stcs(out + 4 * SLOTSZ + obase + (size_t)r * F4, hf[r]);
}

extern "C" void kernel_launch(void* const* d_in, const int* in_sizes, int n_in,
                              void* d_out, int out_size) {
    const float4* x = (const float4*)d_in[0];
    float4* out     = (float4*)d_out;

    const dim3 blk(32, 8);                       // 256 threads
    wavelet_rt_k<<<dim3(S0 / TS, NB), blk>>>(x, out);
}